// round 13
// baseline (speedup 1.0000x reference)
#include <cuda_runtime.h>
#include <cuda_bf16.h>
#include <cstdint>
#include <cstddef>

#define LL 32
#define HH 128
#define KD 130
#define KPE 136           // padded bf16 row (272 B) -> conflict-free LDS.128
#define SPB 2
#define NBLK 256
#define NTHR 256
#define NCELL 1024
#define EPSF 1e-8f
#define W_BYTES  (HH * KPE * 2u)   // 34816
#define AUX_BYTES 2048u
#define TX_BYTES (W_BYTES + AUX_BYTES)

typedef unsigned long long ull;

__device__ unsigned short g_Wb[(size_t)NCELL * HH * KPE];  // bf16 W[:,2:130], padded
__device__ float g_aux[(size_t)NCELL * 512];               // [cell][{w0,w1,b,wf}][n]
__device__ float g_pre[NBLK][SPB][NCELL];                  // deferred pre-activations

struct __align__(16) Smem {
    unsigned short W[2][HH * KPE];  // 69632
    float aux[2][512];              //  4096
    float inp[SPB][2][HH];          //  4096  [half][buf][n] (h-values only)
    float hv[SPB][LL][HH];          // 32768
    float red[SPB][2][4];           //   128
    uint32_t sbits[SPB][LL];        //   256
    ull mbf[2];                     //    16  TMA full
    ull mbc[2];                     //    16  stage consumed (count 2)
};                                  // ~110 KB -> 2 CTAs/SM

__device__ __forceinline__ uint32_t s2u(const void* p) {
    return (uint32_t)__cvta_generic_to_shared(p);
}
__device__ __forceinline__ void mbar_init(uint32_t a, uint32_t c) {
    asm volatile("mbarrier.init.shared::cta.b64 [%0], %1;" :: "r"(a), "r"(c) : "memory");
}
__device__ __forceinline__ void mbar_expect(uint32_t a, uint32_t tx) {
    asm volatile("mbarrier.arrive.expect_tx.shared::cta.b64 _, [%0], %1;" :: "r"(a), "r"(tx) : "memory");
}
__device__ __forceinline__ void mbar_arrive(uint32_t a) {
    asm volatile("mbarrier.arrive.shared::cta.b64 _, [%0];" :: "r"(a) : "memory");
}
__device__ __forceinline__ void tma1d(uint32_t dst, const void* src, uint32_t bytes, uint32_t mbar) {
    asm volatile("cp.async.bulk.shared::cluster.global.mbarrier::complete_tx::bytes [%0], [%1], %2, [%3];"
                 :: "r"(dst), "l"(src), "r"(bytes), "r"(mbar) : "memory");
}
__device__ __forceinline__ void mbar_wait(uint32_t a, uint32_t ph) {
    uint32_t done = 0;
    while (!done) {
        asm volatile("{\n\t.reg .pred p;\n\t"
                     "mbarrier.try_wait.parity.acquire.cta.shared::cta.b64 p, [%1], %2;\n\t"
                     "selp.b32 %0, 1, 0, p;\n\t}"
                     : "=r"(done) : "r"(a), "r"(ph) : "memory");
    }
}
__device__ __forceinline__ void bar_half(int h) {
    asm volatile("bar.sync %0, %1;" :: "r"(1 + h), "r"(128) : "memory");
}
__device__ __forceinline__ float tanh_fast(float x) {
    float y; asm("tanh.approx.f32 %0, %1;" : "=f"(y) : "f"(x)); return y;
}
__device__ __forceinline__ float bflo(uint32_t u) { return __uint_as_float(u << 16); }
__device__ __forceinline__ float bfhi(uint32_t u) { return __uint_as_float(u & 0xffff0000u); }

// ---- prep: W[:,2:130] -> bf16 padded rows; aux pack ----
__global__ void prep_kernel(const float* __restrict__ gW, const float* __restrict__ gB,
                            const float* __restrict__ gWf) {
    const int c = blockIdx.x;
    const float* src = gW + (size_t)c * (HH * KD);
    unsigned short* dst = g_Wb + (size_t)c * (HH * KPE);
    for (int t = threadIdx.x; t < HH * KPE; t += blockDim.x) {
        const int row = t / KPE, col = t - row * KPE;
        __nv_bfloat16 b = __float2bfloat16((col < HH) ? src[row * KD + 2 + col] : 0.f);
        dst[t] = *reinterpret_cast<unsigned short*>(&b);
    }
    float* da = g_aux + (size_t)c * 512;
    for (int t = threadIdx.x; t < 512; t += blockDim.x) {
        const int jj = t >> 7, n = t & 127;
        float v;
        if (jj == 0)      v = src[n * KD + 0];
        else if (jj == 1) v = src[n * KD + 1];
        else if (jj == 2) v = gB[c * HH + n];
        else              v = gWf[c * HH + n];
        da[t] = v;
    }
}

// ---- main: 2 samples/CTA (one per half-block), 2 CTAs/SM ----
__global__ void __launch_bounds__(NTHR, 2)
rnn2d_kernel(const float* __restrict__ gS, const float* __restrict__ gBf,
             float* __restrict__ out)
{
    extern __shared__ unsigned char smem_raw[];
    Smem& s = *reinterpret_cast<Smem*>(smem_raw);
    const int tid = threadIdx.x;
    const int blk = blockIdx.x;
    const int n = tid & 127;        // neuron
    const int h = tid >> 7;         // sample half
    const int lid = tid & 31;

    // ---- init ----
    const float* gs = gS + (size_t)blk * SPB * NCELL;
    if (tid < SPB * LL) {
        const int sm = tid >> 5, row = tid & 31;
        const float* rp = gs + sm * NCELL + row * LL;
        uint32_t bits = 0;
        #pragma unroll
        for (int jj = 0; jj < LL; ++jj) bits |= (rp[jj] > 0.5f ? 1u : 0u) << jj;
        s.sbits[sm][row] = bits;
    }
    for (int t = tid; t < SPB * LL * HH; t += NTHR) ((float*)s.hv)[t] = 0.f;
    for (int t = tid; t < SPB * 2 * HH; t += NTHR) ((float*)s.inp)[t] = 0.f;

    const uint32_t mbf0 = s2u(&s.mbf[0]), mbf1 = s2u(&s.mbf[1]);
    const uint32_t mbc0 = s2u(&s.mbc[0]), mbc1 = s2u(&s.mbc[1]);
    if (tid == 0) {
        mbar_init(mbf0, 1); mbar_init(mbf1, 1);
        mbar_init(mbc0, 2); mbar_init(mbc1, 2);
        asm volatile("fence.mbarrier_init.release.cluster;" ::: "memory");
        mbar_expect(mbf0, TX_BYTES);
        tma1d(s2u(&s.W[0][0]),   g_Wb,                        W_BYTES,   mbf0);
        tma1d(s2u(&s.aux[0][0]), g_aux,                       AUX_BYTES, mbf0);
        mbar_expect(mbf1, TX_BYTES);
        tma1d(s2u(&s.W[1][0]),   g_Wb + (size_t)1 * HH * KPE, W_BYTES,   mbf1);
        tma1d(s2u(&s.aux[1][0]), g_aux + 512,                 AUX_BYTES, mbf1);
    }
    __syncthreads();

    for (int c = 0; c < NCELL; ++c) {
        const int st = c & 1;
        const int r = c >> 5, j = c & 31;
        const int col = (r & 1) ? (LL - 1 - j) : j;

        // deferred pre-activation store for previous cell (warp-1 rep of each half)
        if ((tid & 127) == 32 && c > 0) {
            const int pc = c - 1, pr = pc >> 5, pj = pc & 31;
            const int pcol = (pr & 1) ? (LL - 1 - pj) : pj;
            g_pre[blk][h][(pr << 5) + pcol] =
                s.red[h][pc & 1][0] + s.red[h][pc & 1][1]
              + s.red[h][pc & 1][2] + s.red[h][pc & 1][3];
        }

        mbar_wait(st ? mbf1 : mbf0, (c >> 1) & 1);

        // ---- matvec over the 128 h-inputs (bf16 weights, fp32 accum) ----
        const uint4* Wr = (const uint4*)((const unsigned char*)&s.W[st][0] + n * 272);
        const float4* ip = (const float4*)&s.inp[h][st][0];
        float a0 = 0.f, a1 = 0.f, a2 = 0.f, a3 = 0.f;
        #pragma unroll
        for (int i = 0; i < 16; ++i) {
            const uint4 wp = Wr[i];
            const float4 q0 = ip[2 * i + 0];
            const float4 q1 = ip[2 * i + 1];
            a0 += bflo(wp.x) * q0.x; a1 += bfhi(wp.x) * q0.y;
            a2 += bflo(wp.y) * q0.z; a3 += bfhi(wp.y) * q0.w;
            a0 += bflo(wp.z) * q1.x; a1 += bfhi(wp.z) * q1.y;
            a2 += bflo(wp.w) * q1.z; a3 += bfhi(wp.w) * q1.w;
        }
        const float dot = (a0 + a1) + (a2 + a3);

        // e-features (per-thread, no serialization)
        const int colprev = (r & 1) ? (col + 1) : (col - 1);
        const float xh = (j == 0) ? 0.f : (float)((s.sbits[h][r] >> colprev) & 1u);
        const float xv = (r == 0) ? 0.f : (float)((s.sbits[h][r - 1] >> col) & 1u);
        const float e = xh + xv;

        const float* AUX = s.aux[st];
        const float w0 = AUX[n], w1 = AUX[128 + n];
        const float bb = AUX[256 + n], wf = AUX[384 + n];
        const float hval = tanh_fast(dot + 2.f * bb + w0 * e + w1 * (2.f - e));

        // head partial
        float p = wf * hval;
        #pragma unroll
        for (int o = 16; o; o >>= 1) p += __shfl_xor_sync(0xffffffffu, p, o);
        if (lid == 0) s.red[h][c & 1][(tid >> 5) & 3] = p;

        // hv + next-cell input
        s.hv[h][col][n] = hval;
        if (c + 1 < NCELL) {
            const int cn = c + 1, rn = cn >> 5, jn = cn & 31;
            const int coln = (rn & 1) ? (LL - 1 - jn) : jn;
            const float v = (jn == 0) ? hval : (hval + s.hv[h][coln][n]);
            s.inp[h][(c + 1) & 1][n] = v;
        }

        bar_half(h);

        // stage-consumed bookkeeping + prefetch
        if ((tid & 127) == 0) mbar_arrive(st ? mbc1 : mbc0);
        if (tid == 0 && c + 2 < NCELL) {
            mbar_wait(st ? mbc1 : mbc0, (c >> 1) & 1);
            const int cn = c + 2, rn = cn >> 5, jn = cn & 31;
            const int coln = (rn & 1) ? (LL - 1 - jn) : jn;
            const int celln = (rn << 5) + coln;
            const uint32_t mb = st ? mbf1 : mbf0;
            mbar_expect(mb, TX_BYTES);
            tma1d(s2u(&s.W[st][0]),   g_Wb + (size_t)celln * HH * KPE, W_BYTES,   mb);
            tma1d(s2u(&s.aux[st][0]), g_aux + (size_t)celln * 512,     AUX_BYTES, mb);
        }
    }

    // last cell's pre
    if ((tid & 127) == 32) {
        const int pc = NCELL - 1, pr = pc >> 5, pj = pc & 31;
        const int pcol = (pr & 1) ? (LL - 1 - pj) : pj;
        g_pre[blk][h][(pr << 5) + pcol] =
            s.red[h][pc & 1][0] + s.red[h][pc & 1][1]
          + s.red[h][pc & 1][2] + s.red[h][pc & 1][3];
    }
    __syncthreads();

    // ---- bulk log-prob (per half, 8 cells/thread) ----
    float lp = 0.f;
    for (int c = n; c < NCELL; c += 128) {
        const float pre = g_pre[blk][h][c] + __ldg(gBf + c);
        const int row = c >> 5, bit = c & 31;
        const float m = (float)((s.sbits[h][row] >> bit) & 1u);
        const float xhat = 1.f / (1.f + __expf(-pre));
        lp += m * __logf(xhat + EPSF) + (1.f - m) * __logf(1.f - xhat + EPSF);
    }
    #pragma unroll
    for (int o = 16; o; o >>= 1) lp += __shfl_xor_sync(0xffffffffu, lp, o);
    if (lid == 0) s.red[h][0][(tid >> 5) & 3] = lp;
    bar_half(h);
    if ((tid & 127) == 0)
        out[blk * SPB + h] = s.red[h][0][0] + s.red[h][0][1]
                           + s.red[h][0][2] + s.red[h][0][3];
}

extern "C" void kernel_launch(void* const* d_in, const int* in_sizes, int n_in,
                              void* d_out, int out_size) {
    const float* samples = (const float*)d_in[0];
    const float* W1      = (const float*)d_in[1];
    const float* b1      = (const float*)d_in[2];
    const float* Wf      = (const float*)d_in[3];
    const float* bf      = (const float*)d_in[4];
    float* out = (float*)d_out;

    prep_kernel<<<NCELL, 256>>>(W1, b1, Wf);

    const size_t smem = sizeof(Smem);
    cudaFuncSetAttribute(rnn2d_kernel, cudaFuncAttributeMaxDynamicSharedMemorySize, (int)smem);
    rnn2d_kernel<<<NBLK, NTHR, smem>>>(samples, bf, out);
}

// round 14
// speedup vs baseline: 1.2206x; 1.2206x over previous
#include <cuda_runtime.h>
#include <cuda_bf16.h>
#include <cstdint>
#include <cstddef>

#define LL 32
#define HH 128
#define KD 130
#define KPE 136           // padded bf16 row (272 B) -> conflict-free LDS.128
#define SPB 2
#define NBLK 256
#define NTHR 128
#define NCELL 1024
#define EPSF 1e-8f
#define W_BYTES  (HH * KPE * 2u)   // 34816
#define AUX_BYTES 2048u
#define TX_BYTES (W_BYTES + AUX_BYTES)

typedef unsigned long long ull;

__device__ unsigned short g_Wb[(size_t)NCELL * HH * KPE];  // bf16 W[:,2:130], padded
__device__ float g_aux[(size_t)NCELL * 512];               // [cell][{w0,w1,b,wf}][n]
__device__ float2 g_pre[NBLK][NCELL];                      // deferred pre-activations

struct __align__(16) Smem {
    unsigned short W[2][HH * KPE];  // 69632
    float aux[2][512];              //  4096
    float2 inp[2][HH];              //  2048  [buf][n] = (h s0, h s1)
    float2 hv[LL][HH];              // 32768
    float2 red[2][4];               //    64
    uint32_t sbits[SPB][LL];        //   256
    ull mbar[2];                    //    16
};                                  // ~108.9 KB -> 2 CTAs/SM

__device__ __forceinline__ uint32_t s2u(const void* p) {
    return (uint32_t)__cvta_generic_to_shared(p);
}
__device__ __forceinline__ void mbar_init(uint32_t a, uint32_t c) {
    asm volatile("mbarrier.init.shared::cta.b64 [%0], %1;" :: "r"(a), "r"(c) : "memory");
}
__device__ __forceinline__ void mbar_expect(uint32_t a, uint32_t tx) {
    asm volatile("mbarrier.arrive.expect_tx.shared::cta.b64 _, [%0], %1;" :: "r"(a), "r"(tx) : "memory");
}
__device__ __forceinline__ void tma1d(uint32_t dst, const void* src, uint32_t bytes, uint32_t mbar) {
    asm volatile("cp.async.bulk.shared::cluster.global.mbarrier::complete_tx::bytes [%0], [%1], %2, [%3];"
                 :: "r"(dst), "l"(src), "r"(bytes), "r"(mbar) : "memory");
}
__device__ __forceinline__ void mbar_wait(uint32_t a, uint32_t ph) {
    uint32_t done = 0;
    while (!done) {
        asm volatile("{\n\t.reg .pred p;\n\t"
                     "mbarrier.try_wait.parity.acquire.cta.shared::cta.b64 p, [%1], %2;\n\t"
                     "selp.b32 %0, 1, 0, p;\n\t}"
                     : "=r"(done) : "r"(a), "r"(ph) : "memory");
    }
}
__device__ __forceinline__ float tanh_fast(float x) {
    float y; asm("tanh.approx.f32 %0, %1;" : "=f"(y) : "f"(x)); return y;
}
__device__ __forceinline__ float bflo(uint32_t u) { return __uint_as_float(u << 16); }
__device__ __forceinline__ float bfhi(uint32_t u) { return __uint_as_float(u & 0xffff0000u); }

// ---- prep: W[:,2:130] -> bf16 padded rows; aux pack {w0,w1,b,wf} ----
__global__ void prep_kernel(const float* __restrict__ gW, const float* __restrict__ gB,
                            const float* __restrict__ gWf) {
    const int c = blockIdx.x;
    const float* src = gW + (size_t)c * (HH * KD);
    unsigned short* dst = g_Wb + (size_t)c * (HH * KPE);
    for (int t = threadIdx.x; t < HH * KPE; t += blockDim.x) {
        const int row = t / KPE, col = t - row * KPE;
        __nv_bfloat16 b = __float2bfloat16((col < HH) ? src[row * KD + 2 + col] : 0.f);
        dst[t] = *reinterpret_cast<unsigned short*>(&b);
    }
    float* da = g_aux + (size_t)c * 512;
    for (int t = threadIdx.x; t < 512; t += blockDim.x) {
        const int jj = t >> 7, n = t & 127;
        float v;
        if (jj == 0)      v = src[n * KD + 0];
        else if (jj == 1) v = src[n * KD + 1];
        else if (jj == 2) v = gB[c * HH + n];
        else              v = gWf[c * HH + n];
        da[t] = v;
    }
}

// ---- main: 2 samples/CTA, 2 CTAs/SM (R9 structure, stragglers removed) ----
__global__ void __launch_bounds__(NTHR, 2)
rnn2d_kernel(const float* __restrict__ gS, const float* __restrict__ gBf,
             float* __restrict__ out)
{
    extern __shared__ unsigned char smem_raw[];
    Smem& s = *reinterpret_cast<Smem*>(smem_raw);
    const int tid = threadIdx.x;
    const int blk = blockIdx.x;
    const int n = tid;
    const int lid = tid & 31, wid = tid >> 5;

    // ---- init ----
    const float* gs = gS + (size_t)blk * SPB * NCELL;
    if (tid < SPB * LL) {
        const int sm = tid >> 5, row = tid & 31;
        const float* rp = gs + sm * NCELL + row * LL;
        uint32_t bits = 0;
        #pragma unroll
        for (int jj = 0; jj < LL; ++jj) bits |= (rp[jj] > 0.5f ? 1u : 0u) << jj;
        s.sbits[sm][row] = bits;
    }
    for (int t = tid; t < LL * HH; t += NTHR) ((float2*)s.hv)[t] = make_float2(0.f, 0.f);
    for (int t = tid; t < 2 * HH; t += NTHR) ((float2*)s.inp)[t] = make_float2(0.f, 0.f);

    const uint32_t mb0 = s2u(&s.mbar[0]);
    const uint32_t mb1 = s2u(&s.mbar[1]);
    if (tid == 0) {
        mbar_init(mb0, 1);
        mbar_init(mb1, 1);
        asm volatile("fence.mbarrier_init.release.cluster;" ::: "memory");
        mbar_expect(mb0, TX_BYTES);
        tma1d(s2u(&s.W[0][0]),   g_Wb,  W_BYTES,   mb0);
        tma1d(s2u(&s.aux[0][0]), g_aux, AUX_BYTES, mb0);
    }
    __syncthreads();

    for (int c = 0; c < NCELL; ++c) {
        const int buf = c & 1;
        const int r = c >> 5, j = c & 31;
        const int col = (r & 1) ? (LL - 1 - j) : j;

        // off-path: store previous cell's head sum (tid 32, not the TMA thread)
        if (tid == 32 && c > 0) {
            const int pc = c - 1, pr = pc >> 5, pj = pc & 31;
            const int pcol = (pr & 1) ? (LL - 1 - pj) : pj;
            const float2 q0 = s.red[pc & 1][0], q1 = s.red[pc & 1][1];
            const float2 q2 = s.red[pc & 1][2], q3 = s.red[pc & 1][3];
            g_pre[blk][(pr << 5) + pcol] =
                make_float2(q0.x + q1.x + q2.x + q3.x, q0.y + q1.y + q2.y + q3.y);
        }

        if (tid == 0 && c + 1 < NCELL) {
            const int cn = c + 1, rn = cn >> 5, jn = cn & 31;
            const int coln = (rn & 1) ? (LL - 1 - jn) : jn;
            const int celln = (rn << 5) + coln;
            const uint32_t mb = buf ? mb0 : mb1;
            mbar_expect(mb, TX_BYTES);
            tma1d(s2u(&s.W[buf ^ 1][0]),   g_Wb + (size_t)celln * HH * KPE, W_BYTES,   mb);
            tma1d(s2u(&s.aux[buf ^ 1][0]), g_aux + (size_t)celln * 512,     AUX_BYTES, mb);
        }
        mbar_wait(buf ? mb1 : mb0, (c >> 1) & 1);

        // ---- matvec over 128 h-inputs (bf16 weights, fp32 accumulate) ----
        const uint4* Wr = (const uint4*)((const unsigned char*)&s.W[buf][0] + n * 272);
        const float4* ip = (const float4*)&s.inp[buf][0];
        float a0 = 0.f, a1 = 0.f, b0 = 0.f, b1 = 0.f;
        #pragma unroll
        for (int i = 0; i < 16; ++i) {
            const uint4 wp = Wr[i];
            const float4 q0 = ip[4 * i + 0];
            const float4 q1 = ip[4 * i + 1];
            const float4 q2 = ip[4 * i + 2];
            const float4 q3 = ip[4 * i + 3];
            float w;
            w = bflo(wp.x); a0 += w * q0.x; a1 += w * q0.y;
            w = bfhi(wp.x); b0 += w * q0.z; b1 += w * q0.w;
            w = bflo(wp.y); a0 += w * q1.x; a1 += w * q1.y;
            w = bfhi(wp.y); b0 += w * q1.z; b1 += w * q1.w;
            w = bflo(wp.z); a0 += w * q2.x; a1 += w * q2.y;
            w = bfhi(wp.z); b0 += w * q2.z; b1 += w * q2.w;
            w = bflo(wp.w); a0 += w * q3.x; a1 += w * q3.y;
            w = bfhi(wp.w); b0 += w * q3.z; b1 += w * q3.w;
        }
        const float dot0 = a0 + b0, dot1 = a1 + b1;

        // per-thread e-features (both samples), no serial section
        const int colprev = (r & 1) ? (col + 1) : (col - 1);
        const float xh0 = (j == 0) ? 0.f : (float)((s.sbits[0][r] >> colprev) & 1u);
        const float xv0 = (r == 0) ? 0.f : (float)((s.sbits[0][r - 1] >> col) & 1u);
        const float xh1 = (j == 0) ? 0.f : (float)((s.sbits[1][r] >> colprev) & 1u);
        const float xv1 = (r == 0) ? 0.f : (float)((s.sbits[1][r - 1] >> col) & 1u);
        const float e0 = xh0 + xv0, e1 = xh1 + xv1;

        const float* AUX = s.aux[buf];
        const float w0 = AUX[n], w1 = AUX[128 + n];
        const float bb2 = 2.f * AUX[256 + n], wf = AUX[384 + n];
        const float h0 = tanh_fast(dot0 + bb2 + w0 * e0 + w1 * (2.f - e0));
        const float h1 = tanh_fast(dot1 + bb2 + w0 * e1 + w1 * (2.f - e1));

        // head partials: warp butterfly, lane0 -> smem
        float p0 = wf * h0, p1 = wf * h1;
        #pragma unroll
        for (int o = 16; o; o >>= 1) {
            p0 += __shfl_xor_sync(0xffffffffu, p0, o);
            p1 += __shfl_xor_sync(0xffffffffu, p1, o);
        }
        if (lid == 0) s.red[c & 1][wid] = make_float2(p0, p1);

        // hv + next-cell input
        const float2 hvv = make_float2(h0, h1);
        s.hv[col][n] = hvv;
        if (c + 1 < NCELL) {
            const int cn = c + 1, rn = cn >> 5, jn = cn & 31;
            const int coln = (rn & 1) ? (LL - 1 - jn) : jn;
            float2 v = hvv;
            if (jn != 0) {
                const float2 t = s.hv[coln][n];
                v = make_float2(h0 + t.x, h1 + t.y);
            }
            s.inp[buf ^ 1][n] = v;
        }
        __syncthreads();
    }

    // last cell's pre
    if (tid == 32) {
        const int pc = NCELL - 1, pr = pc >> 5, pj = pc & 31;
        const int pcol = (pr & 1) ? (LL - 1 - pj) : pj;
        const float2 q0 = s.red[pc & 1][0], q1 = s.red[pc & 1][1];
        const float2 q2 = s.red[pc & 1][2], q3 = s.red[pc & 1][3];
        g_pre[blk][(pr << 5) + pcol] =
            make_float2(q0.x + q1.x + q2.x + q3.x, q0.y + q1.y + q2.y + q3.y);
    }
    __syncthreads();

    // ---- bulk log-prob (8 cells/thread) ----
    float lp0 = 0.f, lp1 = 0.f;
    for (int c = tid; c < NCELL; c += NTHR) {
        const float bfv = __ldg(gBf + c);
        const float2 pr = g_pre[blk][c];
        const int row = c >> 5, bit = c & 31;
        float z, xh, m;
        z = pr.x + bfv; xh = 1.f / (1.f + __expf(-z));
        m = (float)((s.sbits[0][row] >> bit) & 1u);
        lp0 += m * __logf(xh + EPSF) + (1.f - m) * __logf(1.f - xh + EPSF);
        z = pr.y + bfv; xh = 1.f / (1.f + __expf(-z));
        m = (float)((s.sbits[1][row] >> bit) & 1u);
        lp1 += m * __logf(xh + EPSF) + (1.f - m) * __logf(1.f - xh + EPSF);
    }
    #pragma unroll
    for (int o = 16; o; o >>= 1) {
        lp0 += __shfl_xor_sync(0xffffffffu, lp0, o);
        lp1 += __shfl_xor_sync(0xffffffffu, lp1, o);
    }
    if (lid == 0) s.red[0][wid] = make_float2(lp0, lp1);
    __syncthreads();
    if (tid < SPB) {
        float acc = 0.f;
        #pragma unroll
        for (int w = 0; w < 4; ++w) acc += ((const float*)&s.red[0][w])[tid];
        out[blk * SPB + tid] = acc;
    }
}

extern "C" void kernel_launch(void* const* d_in, const int* in_sizes, int n_in,
                              void* d_out, int out_size) {
    const float* samples = (const float*)d_in[0];
    const float* W1      = (const float*)d_in[1];
    const float* b1      = (const float*)d_in[2];
    const float* Wf      = (const float*)d_in[3];
    const float* bf      = (const float*)d_in[4];
    float* out = (float*)d_out;

    prep_kernel<<<NCELL, 256>>>(W1, b1, Wf);

    const size_t smem = sizeof(Smem);
    cudaFuncSetAttribute(rnn2d_kernel, cudaFuncAttributeMaxDynamicSharedMemorySize, (int)smem);
    rnn2d_kernel<<<NBLK, NTHR, smem>>>(samples, bf, out);
}

// round 15
// speedup vs baseline: 1.8169x; 1.4885x over previous
#include <cuda_runtime.h>
#include <cuda_bf16.h>
#include <cstdint>
#include <cstddef>

#define LL 32
#define HH 128
#define KD 130
#define KPE 136
#define SPB 2
#define NBLK 256
#define NTHR 128
#define NCELL 1024
#define EPSF 1e-8f
#define W_BYTES  (HH * KPE * 2u)   // 34816
#define AUX_BYTES 2048u
#define TX_BYTES (W_BYTES + AUX_BYTES)

#define OFF_W    0u        // 2 x 34816
#define OFF_AUX  69632u    // 2 x 2048
#define OFF_BT   73728u    // 2 x 2176 (Bt[8][136] bf16)
#define OFF_HV   78080u    // 16384 (u32 bf16x2 [32][128])
#define OFF_RED  94464u    // float2[2][4]
#define OFF_SB   94528u    // 256
#define OFF_MB   94784u    // 16
#define SMEM_SZ  94816u

typedef unsigned long long ull;

__device__ unsigned short g_Wb[(size_t)NCELL * HH * KPE];  // bf16 W[:,2:130], rows padded to 136
__device__ float g_aux[(size_t)NCELL * HH * 4];            // [cell][n][{w0,w1,b,wf}]
__device__ float2 g_pre[NBLK][NCELL];

__device__ __forceinline__ uint32_t s2u(const void* p) {
    return (uint32_t)__cvta_generic_to_shared(p);
}
__device__ __forceinline__ void mbar_init(uint32_t a, uint32_t c) {
    asm volatile("mbarrier.init.shared::cta.b64 [%0], %1;" :: "r"(a), "r"(c) : "memory");
}
__device__ __forceinline__ void mbar_expect(uint32_t a, uint32_t tx) {
    asm volatile("mbarrier.arrive.expect_tx.shared::cta.b64 _, [%0], %1;" :: "r"(a), "r"(tx) : "memory");
}
__device__ __forceinline__ void tma1d(uint32_t dst, const void* src, uint32_t bytes, uint32_t mbar) {
    asm volatile("cp.async.bulk.shared::cluster.global.mbarrier::complete_tx::bytes [%0], [%1], %2, [%3];"
                 :: "r"(dst), "l"(src), "r"(bytes), "r"(mbar) : "memory");
}
__device__ __forceinline__ void mbar_wait(uint32_t a, uint32_t ph) {
    uint32_t done = 0;
    while (!done) {
        asm volatile("{\n\t.reg .pred p;\n\t"
                     "mbarrier.try_wait.parity.acquire.cta.shared::cta.b64 p, [%1], %2;\n\t"
                     "selp.b32 %0, 1, 0, p;\n\t}"
                     : "=r"(done) : "r"(a), "r"(ph) : "memory");
    }
}
__device__ __forceinline__ float tanh_fast(float x) {
    float y; asm("tanh.approx.f32 %0, %1;" : "=f"(y) : "f"(x)); return y;
}
__device__ __forceinline__ float bflo(uint32_t u) { return __uint_as_float(u << 16); }
__device__ __forceinline__ float bfhi(uint32_t u) { return __uint_as_float(u & 0xffff0000u); }
__device__ __forceinline__ uint32_t packbf2(float lo, float hi) {
    uint32_t r; asm("cvt.rn.bf16x2.f32 %0, %2, %1;" : "=r"(r) : "f"(lo), "f"(hi)); return r;
}
__device__ __forceinline__ unsigned short bf16b(float x) {
    unsigned short u; asm("cvt.rn.bf16.f32 %0, %1;" : "=h"(u) : "f"(x)); return u;
}
__device__ __forceinline__ void ldsm4(uint32_t& r0, uint32_t& r1, uint32_t& r2, uint32_t& r3, uint32_t addr) {
    asm volatile("ldmatrix.sync.aligned.m8n8.x4.shared.b16 {%0,%1,%2,%3}, [%4];"
                 : "=r"(r0), "=r"(r1), "=r"(r2), "=r"(r3) : "r"(addr));
}
__device__ __forceinline__ void mma16816(float* c, uint32_t a0, uint32_t a1, uint32_t a2, uint32_t a3,
                                         uint32_t b0, uint32_t b1) {
    asm volatile("mma.sync.aligned.m16n8k16.row.col.f32.bf16.bf16.f32 "
                 "{%0,%1,%2,%3}, {%4,%5,%6,%7}, {%8,%9}, {%0,%1,%2,%3};"
                 : "+f"(c[0]), "+f"(c[1]), "+f"(c[2]), "+f"(c[3])
                 : "r"(a0), "r"(a1), "r"(a2), "r"(a3), "r"(b0), "r"(b1));
}

// ---- prep: W[:,2:130] -> bf16 padded rows; aux pack [n][{w0,w1,b,wf}] ----
__global__ void prep_kernel(const float* __restrict__ gW, const float* __restrict__ gB,
                            const float* __restrict__ gWf) {
    const int c = blockIdx.x;
    const float* src = gW + (size_t)c * (HH * KD);
    unsigned short* dst = g_Wb + (size_t)c * (HH * KPE);
    for (int t = threadIdx.x; t < HH * KPE; t += blockDim.x) {
        const int row = t / KPE, col = t - row * KPE;
        __nv_bfloat16 b = __float2bfloat16((col < HH) ? src[row * KD + 2 + col] : 0.f);
        dst[t] = *reinterpret_cast<unsigned short*>(&b);
    }
    float* da = g_aux + (size_t)c * HH * 4;
    for (int t = threadIdx.x; t < HH; t += blockDim.x) {
        da[t * 4 + 0] = src[t * KD + 0];
        da[t * 4 + 1] = src[t * KD + 1];
        da[t * 4 + 2] = gB[c * HH + t];
        da[t * 4 + 3] = gWf[c * HH + t];
    }
}

// ---- main: mma.sync matvec, 2 samples/CTA, 2 CTAs/SM ----
__global__ void __launch_bounds__(NTHR, 2)
rnn2d_kernel(const float* __restrict__ gS, const float* __restrict__ gBf,
             float* __restrict__ out)
{
    extern __shared__ unsigned char sb[];
    const uint32_t sbu = s2u(sb);
    const int tid = threadIdx.x, blk = blockIdx.x;
    const int lid = tid & 31, wid = tid >> 5;
    const int g = lid >> 2, tr = lid & 3;
    const int wb = wid * 32;

    uint32_t* HV = (uint32_t*)(sb + OFF_HV);
    float2*  RED = (float2*)(sb + OFF_RED);
    uint32_t* SB = (uint32_t*)(sb + OFF_SB);

    // ---- init ----
    const float* gs = gS + (size_t)blk * SPB * NCELL;
    if (tid < SPB * LL) {
        const int sm = tid >> 5, row = tid & 31;
        const float* rp = gs + sm * NCELL + row * LL;
        uint32_t bits = 0;
        #pragma unroll
        for (int jj = 0; jj < LL; ++jj) bits |= (rp[jj] > 0.5f ? 1u : 0u) << jj;
        SB[sm * 32 + row] = bits;
    }
    for (int t = tid; t < 4096; t += NTHR) HV[t] = 0u;                       // hv = 0
    for (int t = tid; t < 1088; t += NTHR) ((uint32_t*)(sb + OFF_BT))[t] = 0u; // Bt both bufs = 0

    const uint32_t mb0 = sbu + OFF_MB, mb1 = sbu + OFF_MB + 8;
    if (tid == 0) {
        mbar_init(mb0, 1);
        mbar_init(mb1, 1);
        asm volatile("fence.mbarrier_init.release.cluster;" ::: "memory");
        mbar_expect(mb0, TX_BYTES);
        tma1d(sbu + OFF_W,   g_Wb,  W_BYTES,   mb0);
        tma1d(sbu + OFF_AUX, g_aux, AUX_BYTES, mb0);
    }
    __syncthreads();

    // ldmatrix lane geometry
    const int mtx = lid >> 3, rowin = lid & 7;
    const int mrow = ((mtx & 1) << 3) + rowin;     // 0..15
    const int kof = (mtx >> 1) << 3;               // 0 or 8

    for (int c = 0; c < NCELL; ++c) {
        const int buf = c & 1;
        const int r = c >> 5, j = c & 31;
        const int col = (r & 1) ? (LL - 1 - j) : j;

        // off-path: previous cell's head sum -> g_pre (tid 32)
        if (tid == 32 && c > 0) {
            const int pc = c - 1, pr = pc >> 5, pj = pc & 31;
            const int pcol = (pr & 1) ? (LL - 1 - pj) : pj;
            const float2 q0 = RED[(pc & 1) * 4 + 0], q1 = RED[(pc & 1) * 4 + 1];
            const float2 q2 = RED[(pc & 1) * 4 + 2], q3 = RED[(pc & 1) * 4 + 3];
            g_pre[blk][(pr << 5) + pcol] =
                make_float2(q0.x + q1.x + q2.x + q3.x, q0.y + q1.y + q2.y + q3.y);
        }
        if (tid == 0 && c + 1 < NCELL) {
            const int cn = c + 1, rn = cn >> 5, jn = cn & 31;
            const int coln = (rn & 1) ? (LL - 1 - jn) : jn;
            const int celln = (rn << 5) + coln;
            const uint32_t mb = buf ? mb0 : mb1;
            mbar_expect(mb, TX_BYTES);
            tma1d(sbu + OFF_W + (buf ^ 1) * W_BYTES,
                  g_Wb + (size_t)celln * HH * KPE, W_BYTES, mb);
            tma1d(sbu + OFF_AUX + (buf ^ 1) * AUX_BYTES,
                  g_aux + (size_t)celln * HH * 4, AUX_BYTES, mb);
        }
        mbar_wait(buf ? mb1 : mb0, (c >> 1) & 1);

        // ---- matvec via mma.sync: M=128 (4 warps x 2 mtiles), N=8, K=128 ----
        float c0[4] = {0.f, 0.f, 0.f, 0.f};
        float c1[4] = {0.f, 0.f, 0.f, 0.f};
        const uint32_t wbase = sbu + OFF_W + buf * W_BYTES;
        const uint32_t a0addr = wbase + (uint32_t)(wb + mrow) * 272u + (uint32_t)kof * 2u;
        const unsigned char* btp = sb + OFF_BT + buf * 2176 + g * 272 + tr * 4;
        #pragma unroll
        for (int kt = 0; kt < 8; ++kt) {
            uint32_t a0, a1, a2, a3, a4, a5, a6, a7;
            ldsm4(a0, a1, a2, a3, a0addr + kt * 32u);
            ldsm4(a4, a5, a6, a7, a0addr + kt * 32u + 16u * 272u);
            const uint32_t b0 = *(const uint32_t*)(btp + kt * 32);
            const uint32_t b1 = *(const uint32_t*)(btp + kt * 32 + 16);
            mma16816(c0, a0, a1, a2, a3, b0, b1);
            mma16816(c1, a4, a5, a6, a7, b0, b1);
        }

        // ---- epilogue ----
        const int colprev = (r & 1) ? (col + 1) : (col - 1);
        const float xh0 = (j == 0) ? 0.f : (float)((SB[r] >> colprev) & 1u);
        const float xv0 = (r == 0) ? 0.f : (float)((SB[r - 1] >> col) & 1u);
        const float xh1 = (j == 0) ? 0.f : (float)((SB[32 + r] >> colprev) & 1u);
        const float xv1 = (r == 0) ? 0.f : (float)((SB[32 + r - 1] >> col) & 1u);
        const float e0 = xh0 + xv0, e1 = xh1 + xv1;

        const float4* AUX = (const float4*)(sb + OFF_AUX + buf * AUX_BYTES);
        const int n0 = wb + g, n1 = wb + g + 8, n2 = wb + g + 16, n3 = wb + g + 24;
        const float4 x0 = AUX[n0], x1 = AUX[n1], x2 = AUX[n2], x3 = AUX[n3];

        const float h00 = tanh_fast(c0[0] + 2.f * x0.z + x0.x * e0 + x0.y * (2.f - e0));
        const float h01 = tanh_fast(c0[1] + 2.f * x0.z + x0.x * e1 + x0.y * (2.f - e1));
        const float h10 = tanh_fast(c0[2] + 2.f * x1.z + x1.x * e0 + x1.y * (2.f - e0));
        const float h11 = tanh_fast(c0[3] + 2.f * x1.z + x1.x * e1 + x1.y * (2.f - e1));
        const float h20 = tanh_fast(c1[0] + 2.f * x2.z + x2.x * e0 + x2.y * (2.f - e0));
        const float h21 = tanh_fast(c1[1] + 2.f * x2.z + x2.x * e1 + x2.y * (2.f - e1));
        const float h30 = tanh_fast(c1[2] + 2.f * x3.z + x3.x * e0 + x3.y * (2.f - e0));
        const float h31 = tanh_fast(c1[3] + 2.f * x3.z + x3.x * e1 + x3.y * (2.f - e1));

        // head partials (only tr==0 lanes hold cols 0,1)
        float p0 = x0.w * h00 + x1.w * h10 + x2.w * h20 + x3.w * h30;
        float p1 = x0.w * h01 + x1.w * h11 + x2.w * h21 + x3.w * h31;
        if (tr != 0) { p0 = 0.f; p1 = 0.f; }
        #pragma unroll
        for (int o = 4; o <= 16; o <<= 1) {
            p0 += __shfl_xor_sync(0xffffffffu, p0, o);
            p1 += __shfl_xor_sync(0xffffffffu, p1, o);
        }
        if (lid == 0) RED[(c & 1) * 4 + wid] = make_float2(p0, p1);

        // hv update + next-cell B build (tr==0 lanes own 4 neurons each)
        if (tr == 0) {
            HV[col * 128 + n0] = packbf2(h00, h01);
            HV[col * 128 + n1] = packbf2(h10, h11);
            HV[col * 128 + n2] = packbf2(h20, h21);
            HV[col * 128 + n3] = packbf2(h30, h31);
            if (c + 1 < NCELL) {
                const int cn = c + 1, rn = cn >> 5, jn = cn & 31;
                const int coln = (rn & 1) ? (LL - 1 - jn) : jn;
                float v00 = h00, v01 = h01, v10 = h10, v11 = h11;
                float v20 = h20, v21 = h21, v30 = h30, v31 = h31;
                if (jn != 0) {
                    const uint32_t t0 = HV[coln * 128 + n0];
                    const uint32_t t1 = HV[coln * 128 + n1];
                    const uint32_t t2 = HV[coln * 128 + n2];
                    const uint32_t t3 = HV[coln * 128 + n3];
                    v00 += bflo(t0); v01 += bfhi(t0);
                    v10 += bflo(t1); v11 += bfhi(t1);
                    v20 += bflo(t2); v21 += bfhi(t2);
                    v30 += bflo(t3); v31 += bfhi(t3);
                }
                unsigned short* bt0 = (unsigned short*)(sb + OFF_BT + (buf ^ 1) * 2176);
                unsigned short* bt1 = bt0 + 136;
                bt0[n0] = bf16b(v00); bt1[n0] = bf16b(v01);
                bt0[n1] = bf16b(v10); bt1[n1] = bf16b(v11);
                bt0[n2] = bf16b(v20); bt1[n2] = bf16b(v21);
                bt0[n3] = bf16b(v30); bt1[n3] = bf16b(v31);
            }
        }
        __syncthreads();
    }

    // last cell's pre
    if (tid == 32) {
        const int pc = NCELL - 1, pr = pc >> 5, pj = pc & 31;
        const int pcol = (pr & 1) ? (LL - 1 - pj) : pj;
        const float2 q0 = RED[(pc & 1) * 4 + 0], q1 = RED[(pc & 1) * 4 + 1];
        const float2 q2 = RED[(pc & 1) * 4 + 2], q3 = RED[(pc & 1) * 4 + 3];
        g_pre[blk][(pr << 5) + pcol] =
            make_float2(q0.x + q1.x + q2.x + q3.x, q0.y + q1.y + q2.y + q3.y);
    }
    __syncthreads();

    // ---- bulk log-prob ----
    float lp0 = 0.f, lp1 = 0.f;
    for (int c = tid; c < NCELL; c += NTHR) {
        const float bfv = __ldg(gBf + c);
        const float2 pr = g_pre[blk][c];
        const int row = c >> 5, bit = c & 31;
        float z, xh, m;
        z = pr.x + bfv; xh = 1.f / (1.f + __expf(-z));
        m = (float)((SB[row] >> bit) & 1u);
        lp0 += m * __logf(xh + EPSF) + (1.f - m) * __logf(1.f - xh + EPSF);
        z = pr.y + bfv; xh = 1.f / (1.f + __expf(-z));
        m = (float)((SB[32 + row] >> bit) & 1u);
        lp1 += m * __logf(xh + EPSF) + (1.f - m) * __logf(1.f - xh + EPSF);
    }
    #pragma unroll
    for (int o = 16; o; o >>= 1) {
        lp0 += __shfl_xor_sync(0xffffffffu, lp0, o);
        lp1 += __shfl_xor_sync(0xffffffffu, lp1, o);
    }
    if (lid == 0) RED[wid] = make_float2(lp0, lp1);
    __syncthreads();
    if (tid < SPB) {
        float acc = 0.f;
        #pragma unroll
        for (int w = 0; w < 4; ++w) acc += ((const float*)&RED[w])[tid];
        out[blk * SPB + tid] = acc;
    }
}

extern "C" void kernel_launch(void* const* d_in, const int* in_sizes, int n_in,
                              void* d_out, int out_size) {
    const float* samples = (const float*)d_in[0];
    const float* W1      = (const float*)d_in[1];
    const float* b1      = (const float*)d_in[2];
    const float* Wf      = (const float*)d_in[3];
    const float* bf      = (const float*)d_in[4];
    float* out = (float*)d_out;

    prep_kernel<<<NCELL, 256>>>(W1, b1, Wf);

    cudaFuncSetAttribute(rnn2d_kernel, cudaFuncAttributeMaxDynamicSharedMemorySize, (int)SMEM_SZ);
    rnn2d_kernel<<<NBLK, NTHR, SMEM_SZ>>>(samples, bf, out);
}